// round 15
// baseline (speedup 1.0000x reference)
#include <cuda_runtime.h>
#include <cuda_bf16.h>
#include <cstddef>
#include <cstring>
#include <cstdint>

#define N_NODES 50000
#define NPAD    50048          // 391*128, tile-padded row count
#define N_EDGES 800000
#define IN_C 128
#define HID_C 128
#define OUT_C 64
#define CSR_BLOCKS 148
#define CSR_THREADS 1024
#define CSR_CHUNK 338          // 148*338 = 50024 >= N_NODES

typedef unsigned long long u64;

// ---------------- scratch (device globals: allocation-free rule) ----------------
__device__ int      g_cnt [N_NODES];                    // ALWAYS zero between calls
__device__ int      g_btot[CSR_BLOCKS];
__device__ int      g_rowptr[N_NODES + 1];
__device__ int      g_wp  [N_NODES];
__device__ u64      g_edge[N_EDGES];                    // packed (src, w)
__device__ unsigned g_bar;                              // monotonic grid-barrier ticket
// packed bf16 hi/lo words (64 words per row = 128 bf16 values)
__device__ __align__(16) uint32_t g_xp_hi[NPAD * 64];   // packed x
__device__ __align__(16) uint32_t g_xp_lo[NPAD * 64];
__device__ __align__(16) uint32_t g_ap_hi[NPAD * 64];   // packed mean-agg(x)
__device__ __align__(16) uint32_t g_ap_lo[NPAD * 64];
__device__ __align__(16) uint32_t g_hp_hi[NPAD * 64];   // packed h (layer-1 out)
__device__ __align__(16) uint32_t g_hp_lo[NPAD * 64];
__device__ __align__(16) uint32_t g_wp1_hi[256 * 64];   // [W_l1; W_r1]
__device__ __align__(16) uint32_t g_wp1_lo[256 * 64];
__device__ __align__(16) uint32_t g_wp2_hi[128 * 64];   // [W_l2; W_r2]
__device__ __align__(16) uint32_t g_wp2_lo[128 * 64];
// fp32 buffers
__device__ __align__(16) float g_r1[N_NODES * HID_C];   // x @ W_r1^T
__device__ __align__(16) float g_y2[N_NODES * OUT_C];
__device__ __align__(16) float g_r2[N_NODES * OUT_C];

// ---------------- helpers ----------------------------------------------------------
__device__ __forceinline__ uint32_t pack_bf16x2(float lo, float hi) {
    uint32_t r;
    asm("cvt.rn.bf16x2.f32 %0, %1, %2;" : "=r"(r) : "f"(hi), "f"(lo));
    return r;
}
__device__ __forceinline__ void bsplit(float x, float& hf, float& lf) {
    __nv_bfloat16 bh = __float2bfloat16(x);
    hf = __bfloat162float(bh);
    lf = x - hf;
}
__device__ __forceinline__ void cvt4(float4 v, uint2& hi, uint2& lo) {
    float h0,h1,h2,h3,l0,l1,l2,l3;
    bsplit(v.x,h0,l0); bsplit(v.y,h1,l1); bsplit(v.z,h2,l2); bsplit(v.w,h3,l3);
    hi = make_uint2(pack_bf16x2(h0,h1), pack_bf16x2(h2,h3));
    lo = make_uint2(pack_bf16x2(l0,l1), pack_bf16x2(l2,l3));
}

// ---------------- prep: pack x + weights into bf16 hi/lo ---------------------------
#define XP_ITEMS (N_NODES * 32)
#define WP1_ITEMS (256 * 32)
#define WP2_ITEMS (128 * 32)
#define PREP_ITEMS (XP_ITEMS + WP1_ITEMS + WP2_ITEMS)

__global__ void prep_kernel(const float* __restrict__ x,
                            const float* __restrict__ W_l1, const float* __restrict__ W_r1,
                            const float* __restrict__ W_l2, const float* __restrict__ W_r2) {
    int idx = blockIdx.x * blockDim.x + threadIdx.x;
    if (idx >= PREP_ITEMS) return;
    uint2 hi, lo;
    if (idx < XP_ITEMS) {
        int row = idx >> 5, q = idx & 31;
        float4 v = *reinterpret_cast<const float4*>(x + (size_t)row * 128 + q * 4);
        cvt4(v, hi, lo);
        *reinterpret_cast<uint2*>(&g_xp_hi[row * 64 + q * 2]) = hi;
        *reinterpret_cast<uint2*>(&g_xp_lo[row * 64 + q * 2]) = lo;
    } else if (idx < XP_ITEMS + WP1_ITEMS) {
        int j = idx - XP_ITEMS;
        int vrow = j >> 5, q = j & 31;
        const float* wr = (vrow < 128) ? (W_l1 + (size_t)vrow * 128)
                                       : (W_r1 + (size_t)(vrow - 128) * 128);
        float4 v = *reinterpret_cast<const float4*>(wr + q * 4);
        cvt4(v, hi, lo);
        *reinterpret_cast<uint2*>(&g_wp1_hi[vrow * 64 + q * 2]) = hi;
        *reinterpret_cast<uint2*>(&g_wp1_lo[vrow * 64 + q * 2]) = lo;
    } else {
        int j = idx - XP_ITEMS - WP1_ITEMS;
        int vrow = j >> 5, q = j & 31;
        const float* wr = (vrow < 64) ? (W_l2 + (size_t)vrow * 128)
                                      : (W_r2 + (size_t)(vrow - 64) * 128);
        float4 v = *reinterpret_cast<const float4*>(wr + q * 4);
        cvt4(v, hi, lo);
        *reinterpret_cast<uint2*>(&g_wp2_hi[vrow * 64 + q * 2]) = hi;
        *reinterpret_cast<uint2*>(&g_wp2_lo[vrow * 64 + q * 2]) = lo;
    }
}

// ---------------- grid barrier (monotonic ticket: replay-safe, no reset) ---------
__device__ __forceinline__ void grid_bar() {
    __shared__ unsigned target;
    __syncthreads();
    if (threadIdx.x == 0) {
        __threadfence();
        unsigned t = atomicAdd(&g_bar, 1u);
        target = (t / CSR_BLOCKS + 1u) * CSR_BLOCKS;
        while (atomicAdd(&g_bar, 0u) < target) { }
        __threadfence();
    }
    __syncthreads();
}

// ---------------- single-launch CSR build (hist + scan + scatter, 3 barriers) -----
__global__ void __launch_bounds__(CSR_THREADS)
csr_kernel(const int* __restrict__ src, const int* __restrict__ dst,
           const float* __restrict__ ew) {
    const int t = threadIdx.x;
    const int b = blockIdx.x;
    const int gt = b * CSR_THREADS + t;
    const int G = CSR_BLOCKS * CSR_THREADS;
    const int lane = t & 31;
    const int wid = t >> 5;
    __shared__ int wsum[32];
    __shared__ int s_boff;

    // --- phase 1: histogram of dst (4-way unrolled, independent REDs) ---
    {
        int e = gt;
        for (; e + 3 * G < N_EDGES; e += 4 * G) {
            int d0 = dst[e], d1 = dst[e + G], d2 = dst[e + 2 * G], d3 = dst[e + 3 * G];
            atomicAdd(&g_cnt[d0], 1);
            atomicAdd(&g_cnt[d1], 1);
            atomicAdd(&g_cnt[d2], 1);
            atomicAdd(&g_cnt[d3], 1);
        }
        for (; e < N_EDGES; e += G) atomicAdd(&g_cnt[dst[e]], 1);
    }
    grid_bar();

    // --- phase 2: scan (read + zero cnt), block totals ---
    const int base = b * CSR_CHUNK;
    const int node = base + t;
    int v = 0;
    if (t < CSR_CHUNK && node < N_NODES) {
        v = __ldcg(&g_cnt[node]);
        g_cnt[node] = 0;                       // leave zeroed for next call
    }

    int inc = v;
#pragma unroll
    for (int off = 1; off < 32; off <<= 1) {
        int u = __shfl_up_sync(0xffffffffu, inc, off);
        if (lane >= off) inc += u;
    }
    if (lane == 31) wsum[wid] = inc;
    __syncthreads();
    if (wid == 0) {
        int wv = wsum[lane];
        int wi = wv;
#pragma unroll
        for (int off = 1; off < 32; off <<= 1) {
            int u = __shfl_up_sync(0xffffffffu, wi, off);
            if (lane >= off) wi += u;
        }
        wsum[lane] = wi;
    }
    __syncthreads();
    int ex = inc - v + ((wid > 0) ? wsum[wid - 1] : 0);
    int btot = wsum[31];
    if (t == 0) g_btot[b] = btot;
    __threadfence();
    grid_bar();

    // --- phase 3: block offset + write rowptr/wp ---
    {
        int contrib = (t < b) ? __ldcg(&g_btot[t]) : 0;
        int r = contrib;
#pragma unroll
        for (int off = 16; off > 0; off >>= 1) r += __shfl_down_sync(0xffffffffu, r, off);
        if (lane == 0) wsum[wid] = r;
        __syncthreads();
        if (wid == 0) {
            int r2 = wsum[lane];
#pragma unroll
            for (int off = 16; off > 0; off >>= 1) r2 += __shfl_down_sync(0xffffffffu, r2, off);
            if (lane == 0) s_boff = r2;
        }
        __syncthreads();
    }
    if (t < CSR_CHUNK && node < N_NODES) {
        int rp = s_boff + ex;
        g_rowptr[node] = rp;
        g_wp[node] = rp;
    }
    if (b == 0 && t == 0) g_rowptr[N_NODES] = N_EDGES;
    __threadfence();
    grid_bar();

    // --- phase 4: scatter packed (src, w) records (4-way unrolled atomics) ---
    {
        int e = gt;
        for (; e + 3 * G < N_EDGES; e += 4 * G) {
            int d0 = dst[e], d1 = dst[e + G], d2 = dst[e + 2 * G], d3 = dst[e + 3 * G];
            int p0 = atomicAdd(&g_wp[d0], 1);
            int p1 = atomicAdd(&g_wp[d1], 1);
            int p2 = atomicAdd(&g_wp[d2], 1);
            int p3 = atomicAdd(&g_wp[d3], 1);
            g_edge[p0] = ((u64)__float_as_uint(ew[e])         << 32) | (unsigned)src[e];
            g_edge[p1] = ((u64)__float_as_uint(ew[e + G])     << 32) | (unsigned)src[e + G];
            g_edge[p2] = ((u64)__float_as_uint(ew[e + 2 * G]) << 32) | (unsigned)src[e + 2 * G];
            g_edge[p3] = ((u64)__float_as_uint(ew[e + 3 * G]) << 32) | (unsigned)src[e + 3 * G];
        }
        for (; e < N_EDGES; e += G) {
            int d = dst[e];
            int pos = atomicAdd(&g_wp[d], 1);
            g_edge[pos] = ((u64)__float_as_uint(ew[e]) << 32) | (unsigned)src[e];
        }
    }
}

// ---------------- gather aggregation -----------------------------------------------
__device__ __forceinline__ void unpack_edge(u64 rec, int& s, float& w) {
    s = (int)(unsigned)rec;
    w = __uint_as_float((unsigned)(rec >> 32));
}

// gatherX: one warp per node over RAW x; emits packed mean-agg(x) (bf16 hi/lo).
__global__ void __launch_bounds__(256)
gatherX_kernel(const float* __restrict__ x) {
    int gt = blockIdx.x * blockDim.x + threadIdx.x;
    int node = gt >> 5;
    if (node >= N_NODES) return;
    int lane = threadIdx.x & 31;

    int beg = g_rowptr[node];
    int end = g_rowptr[node + 1];

    float a0x = 0.f, a0y = 0.f, a0z = 0.f, a0w = 0.f;
    float a1x = 0.f, a1y = 0.f, a1z = 0.f, a1w = 0.f;
    int i = beg;
    for (; i + 8 <= end; i += 8) {
        int   s[8]; float w[8];
#pragma unroll
        for (int q = 0; q < 8; q++) unpack_edge(g_edge[i + q], s[q], w[q]);
        float4 v[8];
#pragma unroll
        for (int q = 0; q < 8; q++)
            v[q] = *reinterpret_cast<const float4*>(x + (size_t)s[q] * 128 + lane * 4);
#pragma unroll
        for (int q = 0; q < 8; q += 2) {
            a0x += w[q]*v[q].x;   a0y += w[q]*v[q].y;
            a0z += w[q]*v[q].z;   a0w += w[q]*v[q].w;
            a1x += w[q+1]*v[q+1].x; a1y += w[q+1]*v[q+1].y;
            a1z += w[q+1]*v[q+1].z; a1w += w[q+1]*v[q+1].w;
        }
    }
    for (; i + 2 <= end; i += 2) {
        int s0, s1; float w0, w1;
        unpack_edge(g_edge[i],   s0, w0);
        unpack_edge(g_edge[i+1], s1, w1);
        float4 v0 = *reinterpret_cast<const float4*>(x + (size_t)s0 * 128 + lane * 4);
        float4 v1 = *reinterpret_cast<const float4*>(x + (size_t)s1 * 128 + lane * 4);
        a0x += w0*v0.x; a0y += w0*v0.y; a0z += w0*v0.z; a0w += w0*v0.w;
        a1x += w1*v1.x; a1y += w1*v1.y; a1z += w1*v1.z; a1w += w1*v1.w;
    }
    if (i < end) {
        int s; float w;
        unpack_edge(g_edge[i], s, w);
        float4 v = *reinterpret_cast<const float4*>(x + (size_t)s * 128 + lane * 4);
        a0x += w*v.x; a0y += w*v.y; a0z += w*v.z; a0w += w*v.w;
    }
    float invd = 1.0f / fmaxf((float)(end - beg), 1.0f);
    float4 o;
    o.x = (a0x + a1x) * invd;
    o.y = (a0y + a1y) * invd;
    o.z = (a0z + a1z) * invd;
    o.w = (a0w + a1w) * invd;

    uint2 hi, lo;
    cvt4(o, hi, lo);
    *reinterpret_cast<uint2*>(&g_ap_hi[node * 64 + lane * 2]) = hi;
    *reinterpret_cast<uint2*>(&g_ap_lo[node * 64 + lane * 2]) = lo;
}

// C=64: one half-warp per node; 8-deep MLP, dual accumulator chains. (final output)
__global__ void __launch_bounds__(256)
gather64_kernel(const float* __restrict__ y, const float* __restrict__ r,
                const float* __restrict__ bias, float* __restrict__ out) {
    int gt = blockIdx.x * blockDim.x + threadIdx.x;
    int node = gt >> 4;
    if (node >= N_NODES) return;
    int lane = threadIdx.x & 15;

    int beg = g_rowptr[node];
    int end = g_rowptr[node + 1];

    float a0x = 0.f, a0y = 0.f, a0z = 0.f, a0w = 0.f;
    float a1x = 0.f, a1y = 0.f, a1z = 0.f, a1w = 0.f;
    int i = beg;
    for (; i + 8 <= end; i += 8) {
        int   s[8]; float w[8];
#pragma unroll
        for (int q = 0; q < 8; q++) unpack_edge(g_edge[i + q], s[q], w[q]);
        float4 v[8];
#pragma unroll
        for (int q = 0; q < 8; q++)
            v[q] = *reinterpret_cast<const float4*>(y + (size_t)s[q] * 64 + lane * 4);
#pragma unroll
        for (int q = 0; q < 8; q += 2) {
            a0x += w[q]*v[q].x;   a0y += w[q]*v[q].y;
            a0z += w[q]*v[q].z;   a0w += w[q]*v[q].w;
            a1x += w[q+1]*v[q+1].x; a1y += w[q+1]*v[q+1].y;
            a1z += w[q+1]*v[q+1].z; a1w += w[q+1]*v[q+1].w;
        }
    }
    for (; i + 2 <= end; i += 2) {
        int s0, s1; float w0, w1;
        unpack_edge(g_edge[i],   s0, w0);
        unpack_edge(g_edge[i+1], s1, w1);
        float4 v0 = *reinterpret_cast<const float4*>(y + (size_t)s0 * 64 + lane * 4);
        float4 v1 = *reinterpret_cast<const float4*>(y + (size_t)s1 * 64 + lane * 4);
        a0x += w0*v0.x; a0y += w0*v0.y; a0z += w0*v0.z; a0w += w0*v0.w;
        a1x += w1*v1.x; a1y += w1*v1.y; a1z += w1*v1.z; a1w += w1*v1.w;
    }
    if (i < end) {
        int s; float w;
        unpack_edge(g_edge[i], s, w);
        float4 v = *reinterpret_cast<const float4*>(y + (size_t)s * 64 + lane * 4);
        a0x += w*v.x; a0y += w*v.y; a0z += w*v.z; a0w += w*v.w;
    }
    float ax = a0x + a1x, ay = a0y + a1y, az = a0z + a1z, aw = a0w + a1w;

    float invd = 1.0f / fmaxf((float)(end - beg), 1.0f);
    float4 r4 = *reinterpret_cast<const float4*>(r + (size_t)node * 64 + lane * 4);
    float4 b4 = *reinterpret_cast<const float4*>(bias + lane * 4);
    float4 o;
    o.x = ax * invd + b4.x + r4.x;
    o.y = ay * invd + b4.y + r4.y;
    o.z = az * invd + b4.z + r4.z;
    o.w = aw * invd + b4.w + r4.w;
    *reinterpret_cast<float4*>(out + (size_t)node * 64 + lane * 4) = o;
}

// ================= bf16 3-term MMA GEMM, cp.async double-buffered =================
#define GSTRIDE 20
#define SA_HI 0
#define SA_LO (128 * GSTRIDE)
#define SW_HI (2 * 128 * GSTRIDE)
#define SW_LO (3 * 128 * GSTRIDE)
#define BUFW  (4 * 128 * GSTRIDE)        // 10240 words per buffer
#define GSM_TOT (2 * BUFW * 4)           // 81920 bytes

#define CP16(dst, src) asm volatile("cp.async.ca.shared.global [%0], [%1], 16;" :: "r"(dst), "l"(src))
#define CP_COMMIT()    asm volatile("cp.async.commit_group;" ::: "memory")
#define CP_WAIT0()     asm volatile("cp.async.wait_group 0;" ::: "memory")

__device__ __forceinline__ void mma_bf16(float* d, const uint32_t* a, const uint32_t* b) {
    asm volatile(
        "mma.sync.aligned.m16n8k16.row.col.f32.bf16.bf16.f32 "
        "{%0,%1,%2,%3}, {%4,%5,%6,%7}, {%8,%9}, {%0,%1,%2,%3};"
        : "+f"(d[0]), "+f"(d[1]), "+f"(d[2]), "+f"(d[3])
        : "r"(a[0]), "r"(a[1]), "r"(a[2]), "r"(a[3]), "r"(b[0]), "r"(b[1]));
}

// Shared mainloop: computes acc for the 128x128 tile starting at row0/col0.
// EPI=0: plain fp32 write to out0/out1 (split routing).
// EPI=1: h = relu(acc + bias + r1), packed bf16 hi/lo into g_hp.
template <int EPI>
__global__ void __launch_bounds__(256, 2)
gemm_mma_kernel(const uint32_t* __restrict__ Ahi, const uint32_t* __restrict__ Alo,
                const uint32_t* __restrict__ Whi, const uint32_t* __restrict__ Wlo,
                float* __restrict__ out0, float* __restrict__ out1,
                const float* __restrict__ bias, const float* __restrict__ radd,
                int split, int n) {
    extern __shared__ __align__(16) uint32_t smu[];
    const int tid = threadIdx.x;
    const int wid = tid >> 5;
    const int lane = tid & 31;
    const int g = lane >> 2;
    const int tg = lane & 3;
    const int row0 = blockIdx.x * 128;
    const int col0 = blockIdx.y * 128;
    const int warp_m = (wid & 1) * 64;
    const int warp_n = (wid >> 1) * 32;

    const int srow = tid >> 1;
    const int shalf = (tid & 1) * 8;
    const uint32_t* gAh = Ahi + (size_t)(row0 + srow) * 64 + shalf;
    const uint32_t* gAl = Alo + (size_t)(row0 + srow) * 64 + shalf;
    const uint32_t* gWh = Whi + (size_t)(col0 + srow) * 64 + shalf;
    const uint32_t* gWl = Wlo + (size_t)(col0 + srow) * 64 + shalf;
    const int sdst = srow * GSTRIDE + shalf;
    const uint32_t sbase = (uint32_t)__cvta_generic_to_shared(smu);

    float acc[4][4][4];
#pragma unroll
    for (int t = 0; t < 4; t++)
#pragma unroll
        for (int u = 0; u < 4; u++)
#pragma unroll
            for (int q = 0; q < 4; q++) acc[t][u][q] = 0.f;

    {
        uint32_t b0 = sbase + 4 * (0 * BUFW + sdst);
        CP16(b0 + 4 * SA_HI,      gAh);     CP16(b0 + 4 * SA_HI + 16, gAh + 4);
        CP16(b0 + 4 * SA_LO,      gAl);     CP16(b0 + 4 * SA_LO + 16, gAl + 4);
        CP16(b0 + 4 * SW_HI,      gWh);     CP16(b0 + 4 * SW_HI + 16, gWh + 4);
        CP16(b0 + 4 * SW_LO,      gWl);     CP16(b0 + 4 * SW_LO + 16, gWl + 4);
        CP_COMMIT();
    }

#pragma unroll
    for (int kc = 0; kc < 4; kc++) {
        CP_WAIT0();
        __syncthreads();
        if (kc < 3) {
            int off = (kc + 1) * 16;
            uint32_t bn = sbase + 4 * (((kc + 1) & 1) * BUFW + sdst);
            CP16(bn + 4 * SA_HI,      gAh + off);   CP16(bn + 4 * SA_HI + 16, gAh + off + 4);
            CP16(bn + 4 * SA_LO,      gAl + off);   CP16(bn + 4 * SA_LO + 16, gAl + off + 4);
            CP16(bn + 4 * SW_HI,      gWh + off);   CP16(bn + 4 * SW_HI + 16, gWh + off + 4);
            CP16(bn + 4 * SW_LO,      gWl + off);   CP16(bn + 4 * SW_LO + 16, gWl + off + 4);
            CP_COMMIT();
        }
        const uint32_t* sb = smu + (kc & 1) * BUFW;

#pragma unroll
        for (int ks = 0; ks < 2; ks++) {
            int pb = ks * 8 + tg;
            uint32_t Af[16], Bf[8], B2[8];
#pragma unroll
            for (int t = 0; t < 4; t++) {
                int r = warp_m + 16 * t + g;
                Af[4*t+0] = sb[SA_HI + r * GSTRIDE + pb];
                Af[4*t+1] = sb[SA_HI + (r + 8) * GSTRIDE + pb];
                Af[4*t+2] = sb[SA_HI + r * GSTRIDE + pb + 4];
                Af[4*t+3] = sb[SA_HI + (r + 8) * GSTRIDE + pb + 4];
            }
#pragma unroll
            for (int u = 0; u < 4; u++) {
                int nn = warp_n + 8 * u + g;
                Bf[2*u+0] = sb[SW_HI + nn * GSTRIDE + pb];
                Bf[2*u+1] = sb[SW_HI + nn * GSTRIDE + pb + 4];
            }
#pragma unroll
            for (int t = 0; t < 4; t++)
#pragma unroll
                for (int u = 0; u < 4; u++)
                    mma_bf16(acc[t][u], &Af[4*t], &Bf[2*u]);
#pragma unroll
            for (int u = 0; u < 4; u++) {
                int nn = warp_n + 8 * u + g;
                B2[2*u+0] = sb[SW_LO + nn * GSTRIDE + pb];
                B2[2*u+1] = sb[SW_LO + nn * GSTRIDE + pb + 4];
            }
#pragma unroll
            for (int t = 0; t < 4; t++)
#pragma unroll
                for (int u = 0; u < 4; u++)
                    mma_bf16(acc[t][u], &Af[4*t], &B2[2*u]);
#pragma unroll
            for (int t = 0; t < 4; t++) {
                int r = warp_m + 16 * t + g;
                Af[4*t+0] = sb[SA_LO + r * GSTRIDE + pb];
                Af[4*t+1] = sb[SA_LO + (r + 8) * GSTRIDE + pb];
                Af[4*t+2] = sb[SA_LO + r * GSTRIDE + pb + 4];
                Af[4*t+3] = sb[SA_LO + (r + 8) * GSTRIDE + pb + 4];
            }
#pragma unroll
            for (int t = 0; t < 4; t++)
#pragma unroll
                for (int u = 0; u < 4; u++)
                    mma_bf16(acc[t][u], &Af[4*t], &Bf[2*u]);
        }
        __syncthreads();
    }

    // ---- epilogue ----
#pragma unroll
    for (int t = 0; t < 4; t++) {
        int r0 = row0 + warp_m + 16 * t + g;
        int r1r = r0 + 8;
#pragma unroll
        for (int u = 0; u < 4; u++) {
            int vc = col0 + warp_n + 8 * u + 2 * tg;
            if (EPI == 0) {
                float* dst0;
                if (vc < split) dst0 = out0 + vc;
                else            dst0 = out1 + (vc - split);
                if (r0 < n)
                    *reinterpret_cast<float2*>(dst0 + (size_t)r0 * split) = make_float2(acc[t][u][0], acc[t][u][1]);
                if (r1r < n)
                    *reinterpret_cast<float2*>(dst0 + (size_t)r1r * split) = make_float2(acc[t][u][2], acc[t][u][3]);
            } else {
                float bc0 = __ldg(bias + vc);
                float bc1 = __ldg(bias + vc + 1);
                if (r0 < n) {
                    float2 rr = *reinterpret_cast<const float2*>(radd + (size_t)r0 * 128 + vc);
                    float h0 = fmaxf(acc[t][u][0] + bc0 + rr.x, 0.f);
                    float h1 = fmaxf(acc[t][u][1] + bc1 + rr.y, 0.f);
                    float hh0, hl0, hh1, hl1;
                    bsplit(h0, hh0, hl0); bsplit(h1, hh1, hl1);
                    g_hp_hi[(size_t)r0 * 64 + (vc >> 1)] = pack_bf16x2(hh0, hh1);
                    g_hp_lo[(size_t)r0 * 64 + (vc >> 1)] = pack_bf16x2(hl0, hl1);
                }
                if (r1r < n) {
                    float2 rr = *reinterpret_cast<const float2*>(radd + (size_t)r1r * 128 + vc);
                    float h0 = fmaxf(acc[t][u][2] + bc0 + rr.x, 0.f);
                    float h1 = fmaxf(acc[t][u][3] + bc1 + rr.y, 0.f);
                    float hh0, hl0, hh1, hl1;
                    bsplit(h0, hh0, hl0); bsplit(h1, hh1, hl1);
                    g_hp_hi[(size_t)r1r * 64 + (vc >> 1)] = pack_bf16x2(hh0, hh1);
                    g_hp_lo[(size_t)r1r * 64 + (vc >> 1)] = pack_bf16x2(hl0, hl1);
                }
            }
        }
    }
}

// ---------------- launch ----------------------------------------------------------
extern "C" void kernel_launch(void* const* d_in, const int* in_sizes, int n_in,
                              void* d_out, int out_size) {
    const float* x    = (const float*)d_in[0];
    const int*   ei   = (const int*)  d_in[1];
    const float* ew   = (const float*)d_in[2];
    // d_in[3] = node_type (unused by the reference)
    const float* W_l1 = (const float*)d_in[4];
    const float* b_l1 = (const float*)d_in[5];
    const float* W_r1 = (const float*)d_in[6];
    const float* W_l2 = (const float*)d_in[7];
    const float* b_l2 = (const float*)d_in[8];
    const float* W_r2 = (const float*)d_in[9];
    float* out = (float*)d_out;

    const int* src = ei;
    const int* dst = ei + N_EDGES;

    float *r1, *y2, *r2;
    uint32_t *xph, *xpl, *aph, *apl, *hph, *hpl, *w1h, *w1l, *w2h, *w2l;
    cudaGetSymbolAddress((void**)&r1, g_r1);
    cudaGetSymbolAddress((void**)&y2, g_y2);
    cudaGetSymbolAddress((void**)&r2, g_r2);
    cudaGetSymbolAddress((void**)&xph, g_xp_hi);
    cudaGetSymbolAddress((void**)&xpl, g_xp_lo);
    cudaGetSymbolAddress((void**)&aph, g_ap_hi);
    cudaGetSymbolAddress((void**)&apl, g_ap_lo);
    cudaGetSymbolAddress((void**)&hph, g_hp_hi);
    cudaGetSymbolAddress((void**)&hpl, g_hp_lo);
    cudaGetSymbolAddress((void**)&w1h, g_wp1_hi);
    cudaGetSymbolAddress((void**)&w1l, g_wp1_lo);
    cudaGetSymbolAddress((void**)&w2h, g_wp2_hi);
    cudaGetSymbolAddress((void**)&w2l, g_wp2_lo);

    cudaFuncSetAttribute(gemm_mma_kernel<0>, cudaFuncAttributeMaxDynamicSharedMemorySize, GSM_TOT);
    cudaFuncSetAttribute(gemm_mma_kernel<1>, cudaFuncAttributeMaxDynamicSharedMemorySize, GSM_TOT);

    const int GB = NPAD / 128;                      // 391

    // one-time side-stream + events (host resources only; no device memory)
    static cudaStream_t s_side = nullptr;
    static cudaEvent_t  ev_fork = nullptr, ev_agg = nullptr;
    if (s_side == nullptr) {
        cudaStreamCreateWithFlags(&s_side, cudaStreamNonBlocking);
        cudaEventCreateWithFlags(&ev_fork, cudaEventDisableTiming);
        cudaEventCreateWithFlags(&ev_agg,  cudaEventDisableTiming);
    }

    // --- side stream: CSR build, then mean-aggregate RAW x (packs agg) ---
    cudaEventRecord(ev_fork, 0);
    cudaStreamWaitEvent(s_side, ev_fork, 0);
    csr_kernel<<<CSR_BLOCKS, CSR_THREADS, 0, s_side>>>(src, dst, ew);
    gatherX_kernel<<<(N_NODES * 32 + 255) / 256, 256, 0, s_side>>>(x);
    cudaEventRecord(ev_agg, s_side);

    // --- main stream (concurrent): pack inputs, then r1 = x @ W_r1^T ---
    prep_kernel<<<(PREP_ITEMS + 255) / 256, 256>>>(x, W_l1, W_r1, W_l2, W_r2);
    gemm_mma_kernel<0><<<dim3(GB, 1), 256, GSM_TOT>>>(
        xph, xpl, w1h + 128 * 64, w1l + 128 * 64, r1, r1, nullptr, nullptr, 128, N_NODES);

    // --- join: h = relu(agg @ W_l1^T + b_l1 + r1), packed bf16 (fused epilogue) ---
    cudaStreamWaitEvent(0, ev_agg, 0);
    gemm_mma_kernel<1><<<dim3(GB, 1), 256, GSM_TOT>>>(
        aph, apl, w1h, w1l, nullptr, nullptr, b_l1, r1, 128, N_NODES);

    // --- layer 2: project h to 64 dims ([W_l2; W_r2] stacked), gather, done ---
    gemm_mma_kernel<0><<<dim3(GB, 1), 256, GSM_TOT>>>(
        hph, hpl, w2h, w2l, y2, r2, nullptr, nullptr, 64, N_NODES);
    gather64_kernel<<<(N_NODES * 16 + 255) / 256, 256>>>(y2, r2, b_l2, out);
}

// round 16
// speedup vs baseline: 1.2244x; 1.2244x over previous
#include <cuda_runtime.h>
#include <cuda_bf16.h>
#include <cuda_fp16.h>
#include <cstddef>
#include <cstring>
#include <cstdint>

#define N_NODES 50000
#define NPAD    50048          // 391*128, tile-padded row count
#define N_EDGES 800000
#define IN_C 128
#define HID_C 128
#define OUT_C 64
#define CSR_BLOCKS 148
#define CSR_THREADS 1024
#define CSR_CHUNK 338          // 148*338 = 50024 >= N_NODES

typedef unsigned long long u64;

// ---------------- scratch (device globals: allocation-free rule) ----------------
__device__ int      g_cnt [N_NODES];                    // ALWAYS zero between calls
__device__ int      g_btot[CSR_BLOCKS];
__device__ int      g_rowptr[N_NODES + 1];
__device__ int      g_wp  [N_NODES];
__device__ u64      g_edge[N_EDGES];                    // packed (src, w)
__device__ unsigned g_bar;                              // monotonic grid-barrier ticket
// packed bf16 hi/lo words (64 words per row = 128 bf16 values)
__device__ __align__(16) uint32_t g_xp_hi[NPAD * 64];
__device__ __align__(16) uint32_t g_xp_lo[NPAD * 64];
__device__ __align__(16) uint32_t g_hp_hi[NPAD * 64];
__device__ __align__(16) uint32_t g_hp_lo[NPAD * 64];
__device__ __align__(16) uint32_t g_wp1_hi[256 * 64];
__device__ __align__(16) uint32_t g_wp1_lo[256 * 64];
__device__ __align__(16) uint32_t g_wp2_hi[128 * 64];
__device__ __align__(16) uint32_t g_wp2_lo[128 * 64];
// gather operands in packed fp16 (f16x2 words); residual terms in fp32
__device__ __align__(16) uint32_t g_y1h[N_NODES * 64];  // y1 = x@W_l1^T, fp16, 128 ch
__device__ __align__(16) uint32_t g_y2h[N_NODES * 32];  // y2 = h@W_l2^T, fp16, 64 ch
__device__ __align__(16) float    g_r1 [N_NODES * HID_C];
__device__ __align__(16) float    g_r2 [N_NODES * OUT_C];

// ---------------- helpers ----------------------------------------------------------
__device__ __forceinline__ uint32_t pack_bf16x2(float lo, float hi) {
    uint32_t r;
    asm("cvt.rn.bf16x2.f32 %0, %1, %2;" : "=r"(r) : "f"(hi), "f"(lo));
    return r;
}
__device__ __forceinline__ uint32_t pack_f16x2(float lo, float hi) {
    uint32_t r;
    asm("cvt.rn.f16x2.f32 %0, %1, %2;" : "=r"(r) : "f"(hi), "f"(lo));
    return r;
}
__device__ __forceinline__ float2 unpack_f16x2(uint32_t w) {
    __half2 h = *reinterpret_cast<__half2*>(&w);
    return __half22float2(h);
}
__device__ __forceinline__ void bsplit(float x, float& hf, float& lf) {
    __nv_bfloat16 bh = __float2bfloat16(x);
    hf = __bfloat162float(bh);
    lf = x - hf;
}
__device__ __forceinline__ void cvt4(float4 v, uint2& hi, uint2& lo) {
    float h0,h1,h2,h3,l0,l1,l2,l3;
    bsplit(v.x,h0,l0); bsplit(v.y,h1,l1); bsplit(v.z,h2,l2); bsplit(v.w,h3,l3);
    hi = make_uint2(pack_bf16x2(h0,h1), pack_bf16x2(h2,h3));
    lo = make_uint2(pack_bf16x2(l0,l1), pack_bf16x2(l2,l3));
}

// ---------------- prep: pack x + weights into bf16 hi/lo ---------------------------
#define XP_ITEMS (N_NODES * 32)
#define WP1_ITEMS (256 * 32)
#define WP2_ITEMS (128 * 32)
#define PREP_ITEMS (XP_ITEMS + WP1_ITEMS + WP2_ITEMS)

__global__ void prep_kernel(const float* __restrict__ x,
                            const float* __restrict__ W_l1, const float* __restrict__ W_r1,
                            const float* __restrict__ W_l2, const float* __restrict__ W_r2) {
    int idx = blockIdx.x * blockDim.x + threadIdx.x;
    if (idx >= PREP_ITEMS) return;
    uint2 hi, lo;
    if (idx < XP_ITEMS) {
        int row = idx >> 5, q = idx & 31;
        float4 v = *reinterpret_cast<const float4*>(x + (size_t)row * 128 + q * 4);
        cvt4(v, hi, lo);
        *reinterpret_cast<uint2*>(&g_xp_hi[row * 64 + q * 2]) = hi;
        *reinterpret_cast<uint2*>(&g_xp_lo[row * 64 + q * 2]) = lo;
    } else if (idx < XP_ITEMS + WP1_ITEMS) {
        int j = idx - XP_ITEMS;
        int vrow = j >> 5, q = j & 31;
        const float* wr = (vrow < 128) ? (W_l1 + (size_t)vrow * 128)
                                       : (W_r1 + (size_t)(vrow - 128) * 128);
        float4 v = *reinterpret_cast<const float4*>(wr + q * 4);
        cvt4(v, hi, lo);
        *reinterpret_cast<uint2*>(&g_wp1_hi[vrow * 64 + q * 2]) = hi;
        *reinterpret_cast<uint2*>(&g_wp1_lo[vrow * 64 + q * 2]) = lo;
    } else {
        int j = idx - XP_ITEMS - WP1_ITEMS;
        int vrow = j >> 5, q = j & 31;
        const float* wr = (vrow < 64) ? (W_l2 + (size_t)vrow * 128)
                                      : (W_r2 + (size_t)(vrow - 64) * 128);
        float4 v = *reinterpret_cast<const float4*>(wr + q * 4);
        cvt4(v, hi, lo);
        *reinterpret_cast<uint2*>(&g_wp2_hi[vrow * 64 + q * 2]) = hi;
        *reinterpret_cast<uint2*>(&g_wp2_lo[vrow * 64 + q * 2]) = lo;
    }
}

// ---------------- grid barrier (monotonic ticket: replay-safe, no reset) ---------
__device__ __forceinline__ void grid_bar() {
    __shared__ unsigned target;
    __syncthreads();
    if (threadIdx.x == 0) {
        __threadfence();
        unsigned t = atomicAdd(&g_bar, 1u);
        target = (t / CSR_BLOCKS + 1u) * CSR_BLOCKS;
        while (atomicAdd(&g_bar, 0u) < target) { }
        __threadfence();
    }
    __syncthreads();
}

// ---------------- single-launch CSR build (hist + scan + scatter, 3 barriers) -----
__global__ void __launch_bounds__(CSR_THREADS)
csr_kernel(const int* __restrict__ src, const int* __restrict__ dst,
           const float* __restrict__ ew) {
    const int t = threadIdx.x;
    const int b = blockIdx.x;
    const int gt = b * CSR_THREADS + t;
    const int G = CSR_BLOCKS * CSR_THREADS;
    const int lane = t & 31;
    const int wid = t >> 5;
    __shared__ int wsum[32];
    __shared__ int s_boff;

    {
        int e = gt;
        for (; e + 3 * G < N_EDGES; e += 4 * G) {
            int d0 = dst[e], d1 = dst[e + G], d2 = dst[e + 2 * G], d3 = dst[e + 3 * G];
            atomicAdd(&g_cnt[d0], 1);
            atomicAdd(&g_cnt[d1], 1);
            atomicAdd(&g_cnt[d2], 1);
            atomicAdd(&g_cnt[d3], 1);
        }
        for (; e < N_EDGES; e += G) atomicAdd(&g_cnt[dst[e]], 1);
    }
    grid_bar();

    const int base = b * CSR_CHUNK;
    const int node = base + t;
    int v = 0;
    if (t < CSR_CHUNK && node < N_NODES) {
        v = __ldcg(&g_cnt[node]);
        g_cnt[node] = 0;                       // leave zeroed for next call
    }

    int inc = v;
#pragma unroll
    for (int off = 1; off < 32; off <<= 1) {
        int u = __shfl_up_sync(0xffffffffu, inc, off);
        if (lane >= off) inc += u;
    }
    if (lane == 31) wsum[wid] = inc;
    __syncthreads();
    if (wid == 0) {
        int wv = wsum[lane];
        int wi = wv;
#pragma unroll
        for (int off = 1; off < 32; off <<= 1) {
            int u = __shfl_up_sync(0xffffffffu, wi, off);
            if (lane >= off) wi += u;
        }
        wsum[lane] = wi;
    }
    __syncthreads();
    int ex = inc - v + ((wid > 0) ? wsum[wid - 1] : 0);
    int btot = wsum[31];
    if (t == 0) g_btot[b] = btot;
    __threadfence();
    grid_bar();

    {
        int contrib = (t < b) ? __ldcg(&g_btot[t]) : 0;
        int r = contrib;
#pragma unroll
        for (int off = 16; off > 0; off >>= 1) r += __shfl_down_sync(0xffffffffu, r, off);
        if (lane == 0) wsum[wid] = r;
        __syncthreads();
        if (wid == 0) {
            int r2 = wsum[lane];
#pragma unroll
            for (int off = 16; off > 0; off >>= 1) r2 += __shfl_down_sync(0xffffffffu, r2, off);
            if (lane == 0) s_boff = r2;
        }
        __syncthreads();
    }
    if (t < CSR_CHUNK && node < N_NODES) {
        int rp = s_boff + ex;
        g_rowptr[node] = rp;
        g_wp[node] = rp;
    }
    if (b == 0 && t == 0) g_rowptr[N_NODES] = N_EDGES;
    __threadfence();
    grid_bar();

    {
        int e = gt;
        for (; e + 3 * G < N_EDGES; e += 4 * G) {
            int d0 = dst[e], d1 = dst[e + G], d2 = dst[e + 2 * G], d3 = dst[e + 3 * G];
            int p0 = atomicAdd(&g_wp[d0], 1);
            int p1 = atomicAdd(&g_wp[d1], 1);
            int p2 = atomicAdd(&g_wp[d2], 1);
            int p3 = atomicAdd(&g_wp[d3], 1);
            g_edge[p0] = ((u64)__float_as_uint(ew[e])         << 32) | (unsigned)src[e];
            g_edge[p1] = ((u64)__float_as_uint(ew[e + G])     << 32) | (unsigned)src[e + G];
            g_edge[p2] = ((u64)__float_as_uint(ew[e + 2 * G]) << 32) | (unsigned)src[e + 2 * G];
            g_edge[p3] = ((u64)__float_as_uint(ew[e + 3 * G]) << 32) | (unsigned)src[e + 3 * G];
        }
        for (; e < N_EDGES; e += G) {
            int d = dst[e];
            int pos = atomicAdd(&g_wp[d], 1);
            g_edge[pos] = ((u64)__float_as_uint(ew[e]) << 32) | (unsigned)src[e];
        }
    }
}

// ---------------- gather aggregation + fused SAGE epilogue ------------------------
__device__ __forceinline__ void unpack_edge(u64 rec, int& s, float& w) {
    s = (int)(unsigned)rec;
    w = __uint_as_float((unsigned)(rec >> 32));
}

// C=128 over fp16 y1 (256 B/row): one warp per node, lane owns 4 channels (uint2).
__global__ void __launch_bounds__(256)
gather128_kernel(const uint32_t* __restrict__ y16, const float* __restrict__ r,
                 const float* __restrict__ bias) {
    int gt = blockIdx.x * blockDim.x + threadIdx.x;
    int node = gt >> 5;
    if (node >= N_NODES) return;
    int lane = threadIdx.x & 31;

    int beg = g_rowptr[node];
    int end = g_rowptr[node + 1];

    float a0x = 0.f, a0y = 0.f, a0z = 0.f, a0w = 0.f;
    float a1x = 0.f, a1y = 0.f, a1z = 0.f, a1w = 0.f;
    int i = beg;
    for (; i + 8 <= end; i += 8) {
        int   s[8]; float w[8];
#pragma unroll
        for (int q = 0; q < 8; q++) unpack_edge(g_edge[i + q], s[q], w[q]);
        uint2 d[8];
#pragma unroll
        for (int q = 0; q < 8; q++)
            d[q] = *reinterpret_cast<const uint2*>(y16 + (size_t)s[q] * 64 + lane * 2);
#pragma unroll
        for (int q = 0; q < 8; q += 2) {
            float2 f0 = unpack_f16x2(d[q].x),   f1 = unpack_f16x2(d[q].y);
            float2 g0 = unpack_f16x2(d[q+1].x), g1 = unpack_f16x2(d[q+1].y);
            a0x += w[q]*f0.x;   a0y += w[q]*f0.y;
            a0z += w[q]*f1.x;   a0w += w[q]*f1.y;
            a1x += w[q+1]*g0.x; a1y += w[q+1]*g0.y;
            a1z += w[q+1]*g1.x; a1w += w[q+1]*g1.y;
        }
    }
    for (; i < end; i++) {
        int s; float w;
        unpack_edge(g_edge[i], s, w);
        uint2 d = *reinterpret_cast<const uint2*>(y16 + (size_t)s * 64 + lane * 2);
        float2 f0 = unpack_f16x2(d.x), f1 = unpack_f16x2(d.y);
        a0x += w*f0.x; a0y += w*f0.y; a0z += w*f1.x; a0w += w*f1.y;
    }
    float ax = a0x + a1x, ay = a0y + a1y, az = a0z + a1z, aw = a0w + a1w;

    float invd = 1.0f / fmaxf((float)(end - beg), 1.0f);
    float4 r4 = *reinterpret_cast<const float4*>(r + (size_t)node * 128 + lane * 4);
    float4 b4 = *reinterpret_cast<const float4*>(bias + lane * 4);
    float4 o;
    o.x = fmaxf(ax * invd + b4.x + r4.x, 0.f);
    o.y = fmaxf(ay * invd + b4.y + r4.y, 0.f);
    o.z = fmaxf(az * invd + b4.z + r4.z, 0.f);
    o.w = fmaxf(aw * invd + b4.w + r4.w, 0.f);

    uint2 hi, lo;
    cvt4(o, hi, lo);
    *reinterpret_cast<uint2*>(&g_hp_hi[node * 64 + lane * 2]) = hi;
    *reinterpret_cast<uint2*>(&g_hp_lo[node * 64 + lane * 2]) = lo;
}

// C=64 over fp16 y2 (128 B/row): half-warp per node, lane owns 4 channels (uint2).
__global__ void __launch_bounds__(256)
gather64_kernel(const uint32_t* __restrict__ y16, const float* __restrict__ r,
                const float* __restrict__ bias, float* __restrict__ out) {
    int gt = blockIdx.x * blockDim.x + threadIdx.x;
    int node = gt >> 4;
    if (node >= N_NODES) return;
    int lane = threadIdx.x & 15;

    int beg = g_rowptr[node];
    int end = g_rowptr[node + 1];

    float a0x = 0.f, a0y = 0.f, a0z = 0.f, a0w = 0.f;
    float a1x = 0.f, a1y = 0.f, a1z = 0.f, a1w = 0.f;
    int i = beg;
    for (; i + 8 <= end; i += 8) {
        int   s[8]; float w[8];
#pragma unroll
        for (int q = 0; q < 8; q++) unpack_edge(g_edge[i + q], s[q], w[q]);
        uint2 d[8];
#pragma unroll
        for (int q = 0; q < 8; q++)
            d[q] = *reinterpret_cast<const uint2*>(y16 + (size_t)s[q] * 32 + lane * 2);
#pragma unroll
        for (int q = 0; q < 8; q += 2) {
            float2 f0 = unpack_f16x2(d[q].x),   f1 = unpack_f16x2(d[q].y);
            float2 g0 = unpack_f16x2(d[q+1].x), g1 = unpack_f16x2(d[q+1].y);
            a0x += w[q]*f0.x;   a0y += w[q]*f0.y;
            a0z += w[q]*f1.x;   a0w += w[q]*f1.y;
            a1x += w[q+1]*g0.x; a1y += w[q+1]*g0.y;
            a1z += w[q+1]*g1.x; a1w += w[q+1]*g1.y;
        }
    }
    for (; i < end; i++) {
        int s; float w;
        unpack_edge(g_edge[i], s, w);
        uint2 d = *reinterpret_cast<const uint2*>(y16 + (size_t)s * 32 + lane * 2);
        float2 f0 = unpack_f16x2(d.x), f1 = unpack_f16x2(d.y);
        a0x += w*f0.x; a0y += w*f0.y; a0z += w*f1.x; a0w += w*f1.y;
    }
    float ax = a0x + a1x, ay = a0y + a1y, az = a0z + a1z, aw = a0w + a1w;

    float invd = 1.0f / fmaxf((float)(end - beg), 1.0f);
    float4 r4 = *reinterpret_cast<const float4*>(r + (size_t)node * 64 + lane * 4);
    float4 b4 = *reinterpret_cast<const float4*>(bias + lane * 4);
    float4 o;
    o.x = ax * invd + b4.x + r4.x;
    o.y = ay * invd + b4.y + r4.y;
    o.z = az * invd + b4.z + r4.z;
    o.w = aw * invd + b4.w + r4.w;
    *reinterpret_cast<float4*>(out + (size_t)node * 64 + lane * 4) = o;
}

// ================= bf16 3-term MMA GEMM, cp.async double-buffered =================
// Epilogue: cols [0, split) -> fp16x2 packed into out0h (row stride split/2 words);
//           cols [split, ...) -> fp32 into out1 (row stride split floats).
#define GSTRIDE 20
#define SA_HI 0
#define SA_LO (128 * GSTRIDE)
#define SW_HI (2 * 128 * GSTRIDE)
#define SW_LO (3 * 128 * GSTRIDE)
#define BUFW  (4 * 128 * GSTRIDE)        // 10240 words per buffer
#define GSM_TOT (2 * BUFW * 4)           // 81920 bytes

#define CP16(dst, src) asm volatile("cp.async.ca.shared.global [%0], [%1], 16;" :: "r"(dst), "l"(src))
#define CP_COMMIT()    asm volatile("cp.async.commit_group;" ::: "memory")
#define CP_WAIT0()     asm volatile("cp.async.wait_group 0;" ::: "memory")

__device__ __forceinline__ void mma_bf16(float* d, const uint32_t* a, const uint32_t* b) {
    asm volatile(
        "mma.sync.aligned.m16n8k16.row.col.f32.bf16.bf16.f32 "
        "{%0,%1,%2,%3}, {%4,%5,%6,%7}, {%8,%9}, {%0,%1,%2,%3};"
        : "+f"(d[0]), "+f"(d[1]), "+f"(d[2]), "+f"(d[3])
        : "r"(a[0]), "r"(a[1]), "r"(a[2]), "r"(a[3]), "r"(b[0]), "r"(b[1]));
}

__global__ void __launch_bounds__(256, 2)
gemm_mma_kernel(const uint32_t* __restrict__ Ahi, const uint32_t* __restrict__ Alo,
                const uint32_t* __restrict__ Whi, const uint32_t* __restrict__ Wlo,
                uint32_t* __restrict__ out0h, float* __restrict__ out1,
                int split, int n) {
    extern __shared__ __align__(16) uint32_t smu[];
    const int tid = threadIdx.x;
    const int wid = tid >> 5;
    const int lane = tid & 31;
    const int g = lane >> 2;
    const int tg = lane & 3;
    const int row0 = blockIdx.x * 128;
    const int col0 = blockIdx.y * 128;
    const int warp_m = (wid & 1) * 64;
    const int warp_n = (wid >> 1) * 32;

    const int srow = tid >> 1;
    const int shalf = (tid & 1) * 8;
    const uint32_t* gAh = Ahi + (size_t)(row0 + srow) * 64 + shalf;
    const uint32_t* gAl = Alo + (size_t)(row0 + srow) * 64 + shalf;
    const uint32_t* gWh = Whi + (size_t)(col0 + srow) * 64 + shalf;
    const uint32_t* gWl = Wlo + (size_t)(col0 + srow) * 64 + shalf;
    const int sdst = srow * GSTRIDE + shalf;
    const uint32_t sbase = (uint32_t)__cvta_generic_to_shared(smu);

    float acc[4][4][4];
#pragma unroll
    for (int t = 0; t < 4; t++)
#pragma unroll
        for (int u = 0; u < 4; u++)
#pragma unroll
            for (int q = 0; q < 4; q++) acc[t][u][q] = 0.f;

    {
        uint32_t b0 = sbase + 4 * (0 * BUFW + sdst);
        CP16(b0 + 4 * SA_HI,      gAh);     CP16(b0 + 4 * SA_HI + 16, gAh + 4);
        CP16(b0 + 4 * SA_LO,      gAl);     CP16(b0 + 4 * SA_LO + 16, gAl + 4);
        CP16(b0 + 4 * SW_HI,      gWh);     CP16(b0 + 4 * SW_HI + 16, gWh + 4);
        CP16(b0 + 4 * SW_LO,      gWl);     CP16(b0 + 4 * SW_LO + 16, gWl + 4);
        CP_COMMIT();
    }

#pragma unroll
    for (int kc = 0; kc < 4; kc++) {
        CP_WAIT0();
        __syncthreads();
        if (kc < 3) {
            int off = (kc + 1) * 16;
            uint32_t bn = sbase + 4 * (((kc + 1) & 1) * BUFW + sdst);
            CP16(bn + 4 * SA_HI,      gAh + off);   CP16(bn + 4 * SA_HI + 16, gAh + off + 4);
            CP16(bn + 4 * SA_LO,      gAl + off);   CP16(bn + 4 * SA_LO + 16, gAl + off + 4);
            CP16(bn + 4 * SW_HI,      gWh + off);   CP16(bn + 4 * SW_HI + 16, gWh + off + 4);
            CP16(bn + 4 * SW_LO,      gWl + off);   CP16(bn + 4 * SW_LO + 16, gWl + off + 4);
            CP_COMMIT();
        }
        const uint32_t* sb = smu + (kc & 1) * BUFW;

#pragma unroll
        for (int ks = 0; ks < 2; ks++) {
            int pb = ks * 8 + tg;
            uint32_t Af[16], Bf[8], B2[8];
#pragma unroll
            for (int t = 0; t < 4; t++) {
                int r = warp_m + 16 * t + g;
                Af[4*t+0] = sb[SA_HI + r * GSTRIDE + pb];
                Af[4*t+1] = sb[SA_HI + (r + 8) * GSTRIDE + pb];
                Af[4*t+2] = sb[SA_HI + r * GSTRIDE + pb + 4];
                Af[4*t+3] = sb[SA_HI + (r + 8) * GSTRIDE + pb + 4];
            }
#pragma unroll
            for (int u = 0; u < 4; u++) {
                int nn = warp_n + 8 * u + g;
                Bf[2*u+0] = sb[SW_HI + nn * GSTRIDE + pb];
                Bf[2*u+1] = sb[SW_HI + nn * GSTRIDE + pb + 4];
            }
#pragma unroll
            for (int t = 0; t < 4; t++)
#pragma unroll
                for (int u = 0; u < 4; u++)
                    mma_bf16(acc[t][u], &Af[4*t], &Bf[2*u]);
#pragma unroll
            for (int u = 0; u < 4; u++) {
                int nn = warp_n + 8 * u + g;
                B2[2*u+0] = sb[SW_LO + nn * GSTRIDE + pb];
                B2[2*u+1] = sb[SW_LO + nn * GSTRIDE + pb + 4];
            }
#pragma unroll
            for (int t = 0; t < 4; t++)
#pragma unroll
                for (int u = 0; u < 4; u++)
                    mma_bf16(acc[t][u], &Af[4*t], &B2[2*u]);
#pragma unroll
            for (int t = 0; t < 4; t++) {
                int r = warp_m + 16 * t + g;
                Af[4*t+0] = sb[SA_LO + r * GSTRIDE + pb];
                Af[4*t+1] = sb[SA_LO + (r + 8) * GSTRIDE + pb];
                Af[4*t+2] = sb[SA_LO + r * GSTRIDE + pb + 4];
                Af[4*t+3] = sb[SA_LO + (r + 8) * GSTRIDE + pb + 4];
            }
#pragma unroll
            for (int t = 0; t < 4; t++)
#pragma unroll
                for (int u = 0; u < 4; u++)
                    mma_bf16(acc[t][u], &Af[4*t], &Bf[2*u]);
        }
        __syncthreads();
    }

    // ---- epilogue: fp16 pack for cols < split, fp32 otherwise ----
    const int hstride = split >> 1;
#pragma unroll
    for (int t = 0; t < 4; t++) {
        int r0 = row0 + warp_m + 16 * t + g;
        int r1 = r0 + 8;
#pragma unroll
        for (int u = 0; u < 4; u++) {
            int vc = col0 + warp_n + 8 * u + 2 * tg;
            if (vc < split) {
                if (r0 < n)
                    out0h[(size_t)r0 * hstride + (vc >> 1)] = pack_f16x2(acc[t][u][0], acc[t][u][1]);
                if (r1 < n)
                    out0h[(size_t)r1 * hstride + (vc >> 1)] = pack_f16x2(acc[t][u][2], acc[t][u][3]);
            } else {
                float* dst0 = out1 + (vc - split);
                if (r0 < n)
                    *reinterpret_cast<float2*>(dst0 + (size_t)r0 * split) = make_float2(acc[t][u][0], acc[t][u][1]);
                if (r1 < n)
                    *reinterpret_cast<float2*>(dst0 + (size_t)r1 * split) = make_float2(acc[t][u][2], acc[t][u][3]);
            }
        }
    }
}

// ---------------- launch ----------------------------------------------------------
extern "C" void kernel_launch(void* const* d_in, const int* in_sizes, int n_in,
                              void* d_out, int out_size) {
    const float* x    = (const float*)d_in[0];
    const int*   ei   = (const int*)  d_in[1];
    const float* ew   = (const float*)d_in[2];
    // d_in[3] = node_type (unused by the reference)
    const float* W_l1 = (const float*)d_in[4];
    const float* b_l1 = (const float*)d_in[5];
    const float* W_r1 = (const float*)d_in[6];
    const float* W_l2 = (const float*)d_in[7];
    const float* b_l2 = (const float*)d_in[8];
    const float* W_r2 = (const float*)d_in[9];
    float* out = (float*)d_out;

    const int* src = ei;
    const int* dst = ei + N_EDGES;

    float *r1, *r2;
    uint32_t *xph, *xpl, *hph, *hpl, *w1h, *w1l, *w2h, *w2l, *y1h, *y2h;
    cudaGetSymbolAddress((void**)&r1, g_r1);
    cudaGetSymbolAddress((void**)&r2, g_r2);
    cudaGetSymbolAddress((void**)&xph, g_xp_hi);
    cudaGetSymbolAddress((void**)&xpl, g_xp_lo);
    cudaGetSymbolAddress((void**)&hph, g_hp_hi);
    cudaGetSymbolAddress((void**)&hpl, g_hp_lo);
    cudaGetSymbolAddress((void**)&w1h, g_wp1_hi);
    cudaGetSymbolAddress((void**)&w1l, g_wp1_lo);
    cudaGetSymbolAddress((void**)&w2h, g_wp2_hi);
    cudaGetSymbolAddress((void**)&w2l, g_wp2_lo);
    cudaGetSymbolAddress((void**)&y1h, g_y1h);
    cudaGetSymbolAddress((void**)&y2h, g_y2h);

    cudaFuncSetAttribute(gemm_mma_kernel, cudaFuncAttributeMaxDynamicSharedMemorySize, GSM_TOT);

    const int GB = NPAD / 128;                      // 391

    // one-time side-stream + events (host resources only; no device memory)
    static cudaStream_t s_side = nullptr;
    static cudaEvent_t  ev_fork = nullptr, ev_join = nullptr;
    if (s_side == nullptr) {
        cudaStreamCreateWithFlags(&s_side, cudaStreamNonBlocking);
        cudaEventCreateWithFlags(&ev_fork, cudaEventDisableTiming);
        cudaEventCreateWithFlags(&ev_join, cudaEventDisableTiming);
    }

    // --- fork: lean CSR build (side stream) concurrent with prep + layer-1 GEMM ---
    cudaEventRecord(ev_fork, 0);
    cudaStreamWaitEvent(s_side, ev_fork, 0);
    csr_kernel<<<CSR_BLOCKS, CSR_THREADS, 0, s_side>>>(src, dst, ew);
    cudaEventRecord(ev_join, s_side);

    prep_kernel<<<(PREP_ITEMS + 255) / 256, 256>>>(x, W_l1, W_r1, W_l2, W_r2);
    gemm_mma_kernel<<<dim3(GB, 2), 256, GSM_TOT>>>(xph, xpl, w1h, w1l, y1h, r1, 128, N_NODES);

    // --- join: gather needs both CSR and GEMM outputs ---
    cudaStreamWaitEvent(0, ev_join, 0);
    gather128_kernel<<<(N_NODES * 32 + 255) / 256, 256>>>(y1h, r1, b_l1);

    // --- layer 2 ---
    gemm_mma_kernel<<<dim3(GB, 1), 256, GSM_TOT>>>(hph, hpl, w2h, w2l, y2h, r2, 64, N_NODES);
    gather64_kernel<<<(N_NODES * 16 + 255) / 256, 256>>>(y2h, r2, b_l2, out);
}